// round 10
// baseline (speedup 1.0000x reference)
#include <cuda_runtime.h>
#include <math.h>

// ------------------------------------------------------------------
// B=16, C=256, H=W=64, K=3, 5 param matrices 256x256
// ------------------------------------------------------------------
#define MATSZ 65536  // 256*256
typedef unsigned long long ull;

// ---------------- device scratch (no allocations) -----------------
__device__ float g_s[5];
__device__ float g_wa[5][MATSZ];
__device__ float g_wb[5][MATSZ];
__device__ float g_wtw[5][MATSZ];
__device__ float g_PQ[4][MATSZ];
__device__ float g_C2[2][MATSZ];
__device__ float g_blk[2][4][MATSZ];
__device__ float g_p9[9][MATSZ];
__device__ float g_W9[9][MATSZ];   // [kh*3+kw][ic*256+oc]

// ---------------- packed f32x2 helpers -----------------------------
#define PACK2(d, lo, hi) \
    asm("mov.b64 %0, {%1, %2};" : "=l"(d) : "f"(lo), "f"(hi))
#define UNPACK2(lo, hi, v) \
    asm("mov.b64 {%0, %1}, %2;" : "=f"(lo), "=f"(hi) : "l"(v))
#define FMA2(acc, a, b) \
    asm("fma.rn.f32x2 %0, %1, %2, %0;" : "+l"(acc) : "l"(a), "l"(b))

// ---------------- RNG: threefry2x32 (JAX partitionable) ------------
__device__ __forceinline__ unsigned rotl32(unsigned x, int d) {
    return (x << d) | (x >> (32 - d));
}

__device__ __forceinline__ void threefry2x32(unsigned k0, unsigned k1,
                                             unsigned& x0, unsigned& x1) {
    unsigned ks[3] = {k0, k1, k0 ^ k1 ^ 0x1BD11BDAu};
    const int r0[4] = {13, 15, 26, 6};
    const int r1[4] = {17, 29, 16, 24};
    x0 += ks[0]; x1 += ks[1];
#pragma unroll
    for (int i = 0; i < 5; i++) {
        const int* R = ((i & 1) == 0) ? r0 : r1;
#pragma unroll
        for (int j = 0; j < 4; j++) {
            x0 += x1;
            x1 = rotl32(x1, R[j]);
            x1 ^= x0;
        }
        x0 += ks[(i + 1) % 3];
        x1 += ks[(i + 2) % 3] + (unsigned)(i + 1);
    }
}

// XLA f32 erf_inv (Giles polynomial)
__device__ __forceinline__ float erfinv_f(float x) {
    float w = -log1pf(-x * x);
    float p;
    if (w < 5.0f) {
        w = w - 2.5f;
        p = 2.81022636e-08f;
        p = fmaf(p, w, 3.43273939e-07f);
        p = fmaf(p, w, -3.5233877e-06f);
        p = fmaf(p, w, -4.39150654e-06f);
        p = fmaf(p, w, 0.00021858087f);
        p = fmaf(p, w, -0.00125372503f);
        p = fmaf(p, w, -0.00417768164f);
        p = fmaf(p, w, 0.246640727f);
        p = fmaf(p, w, 1.50140941f);
    } else {
        w = sqrtf(w) - 3.0f;
        p = -0.000200214257f;
        p = fmaf(p, w, 0.000100950558f);
        p = fmaf(p, w, 0.00134934322f);
        p = fmaf(p, w, -0.00367342844f);
        p = fmaf(p, w, 0.00573950773f);
        p = fmaf(p, w, -0.0076224613f);
        p = fmaf(p, w, 0.00943887047f);
        p = fmaf(p, w, 1.00167406f);
        p = fmaf(p, w, 2.83297682f);
    }
    return p * x;
}

__device__ __forceinline__ float block_sum256(float v, float* red) {
    int t = threadIdx.x;
    red[t] = v;
    __syncthreads();
#pragma unroll
    for (int s = 128; s > 0; s >>= 1) {
        if (t < s) red[t] += red[t + s];
        __syncthreads();
    }
    float r = red[0];
    __syncthreads();
    return r;
}

// ---------------- kernel 1: RNG + power iteration ------------------
__global__ void pi_kernel(const float* __restrict__ pm) {
    __shared__ float su[256], sv[256], red[256];
    int b = blockIdx.x, t = threadIdx.x;

    unsigned idx = (unsigned)(b * 256 + t);     // 0..1279
    unsigned x0 = 0u, x1 = idx;
    threefry2x32(0u, 1u, x0, x1);
    unsigned bits = x1;                          // low word of 64-bit output
    float f = __uint_as_float((bits >> 9) | 0x3f800000u) - 1.0f;   // [0,1)
    const float lo = -0.99999994f;                                  // nextafter(-1,0)
    float val = fmaxf(lo, f * (1.0f - lo) + lo);
    su[t] = 1.41421354f * erfinv_f(val);
    __syncthreads();

    const float* A = pm + (size_t)b * MATSZ;
    float lastnorm = 1.0f;
    for (int it = 0; it < 10; it++) {
        float acc = 0.0f;
        for (int i = 0; i < 256; i++) acc = fmaf(A[i * 256 + t], su[i], acc);
        float nv = sqrtf(block_sum256(acc * acc, red));
        sv[t] = acc / nv;
        __syncthreads();
        float acc2 = 0.0f;
        for (int j = 0; j < 256; j++) acc2 = fmaf(A[t * 256 + j], sv[j], acc2);
        float nu = sqrtf(block_sum256(acc2 * acc2, red));
        su[t] = acc2 / nu;
        __syncthreads();
        lastnorm = nu;
    }
    if (t == 0) g_s[b] = lastnorm;
}

// w = pm / s[b]
__global__ void scale_kernel(const float* __restrict__ pm) {
    int i = blockIdx.x * 256 + threadIdx.x;
    ((float*)g_wa)[i] = pm[i] / g_s[i >> 16];
}

// ---------------- tiled GEMM helpers (64x64 tile, 256 thr) ---------
#define FMA16(a, bb)                                                              \
    do {                                                                          \
        acc[0][0] = fmaf(a.x, bb.x, acc[0][0]); acc[0][1] = fmaf(a.x, bb.y, acc[0][1]); \
        acc[0][2] = fmaf(a.x, bb.z, acc[0][2]); acc[0][3] = fmaf(a.x, bb.w, acc[0][3]); \
        acc[1][0] = fmaf(a.y, bb.x, acc[1][0]); acc[1][1] = fmaf(a.y, bb.y, acc[1][1]); \
        acc[1][2] = fmaf(a.y, bb.z, acc[1][2]); acc[1][3] = fmaf(a.y, bb.w, acc[1][3]); \
        acc[2][0] = fmaf(a.z, bb.x, acc[2][0]); acc[2][1] = fmaf(a.z, bb.y, acc[2][1]); \
        acc[2][2] = fmaf(a.z, bb.z, acc[2][2]); acc[2][3] = fmaf(a.z, bb.w, acc[2][3]); \
        acc[3][0] = fmaf(a.w, bb.x, acc[3][0]); acc[3][1] = fmaf(a.w, bb.y, acc[3][1]); \
        acc[3][2] = fmaf(a.w, bb.z, acc[3][2]); acc[3][3] = fmaf(a.w, bb.w, acc[3][3]); \
    } while (0)

// C[i,k] += sum_j A[i,j]*B[j,k]
__device__ __forceinline__ void gemm_nn_tile(const float* __restrict__ A,
                                             const float* __restrict__ B,
                                             int I0, int K0, int Klen,
                                             float (&acc)[4][4],
                                             float (*As)[64], float (*Bs)[64]) {
    int tid = threadIdx.x;
    int lr = tid >> 2, lc4 = (tid & 3) * 4;
    int bk = tid >> 4, bi4 = (tid & 15) * 4;
    int tx = tid & 15, ty = tid >> 4;
    for (int j0 = 0; j0 < Klen; j0 += 16) {
        float4 av = *(const float4*)&A[(I0 + lr) * 256 + j0 + lc4];
        As[lc4 + 0][lr] = av.x; As[lc4 + 1][lr] = av.y;
        As[lc4 + 2][lr] = av.z; As[lc4 + 3][lr] = av.w;
        *(float4*)&Bs[bk][bi4] = *(const float4*)&B[(j0 + bk) * 256 + K0 + bi4];
        __syncthreads();
#pragma unroll
        for (int kk = 0; kk < 16; kk++) {
            float4 a  = *(float4*)&As[kk][ty * 4];
            float4 bb = *(float4*)&Bs[kk][tx * 4];
            FMA16(a, bb);
        }
        __syncthreads();
    }
}

// C[i,k] += sum_j A[i,j]*B[k,j]
__device__ __forceinline__ void gemm_nt_tile(const float* __restrict__ A,
                                             const float* __restrict__ B,
                                             int I0, int K0, int Klen,
                                             float (&acc)[4][4],
                                             float (*As)[64], float (*Bs)[64]) {
    int tid = threadIdx.x;
    int lr = tid >> 2, lc4 = (tid & 3) * 4;
    int tx = tid & 15, ty = tid >> 4;
    for (int j0 = 0; j0 < Klen; j0 += 16) {
        float4 av = *(const float4*)&A[(I0 + lr) * 256 + j0 + lc4];
        As[lc4 + 0][lr] = av.x; As[lc4 + 1][lr] = av.y;
        As[lc4 + 2][lr] = av.z; As[lc4 + 3][lr] = av.w;
        float4 bv = *(const float4*)&B[(K0 + lr) * 256 + j0 + lc4];
        Bs[lc4 + 0][lr] = bv.x; Bs[lc4 + 1][lr] = bv.y;
        Bs[lc4 + 2][lr] = bv.z; Bs[lc4 + 3][lr] = bv.w;
        __syncthreads();
#pragma unroll
        for (int kk = 0; kk < 16; kk++) {
            float4 a  = *(float4*)&As[kk][ty * 4];
            float4 bb = *(float4*)&Bs[kk][tx * 4];
            FMA16(a, bb);
        }
        __syncthreads();
    }
}

__device__ __forceinline__ void store_tile(float* __restrict__ C, int I0, int K0,
                                           float (&acc)[4][4]) {
    int tx = threadIdx.x & 15, ty = threadIdx.x >> 4;
#pragma unroll
    for (int r = 0; r < 4; r++) {
        float4 v;
        v.x = acc[r][0]; v.y = acc[r][1]; v.z = acc[r][2]; v.w = acc[r][3];
        *(float4*)&C[(I0 + ty * 4 + r) * 256 + K0 + tx * 4] = v;
    }
}

// ---------------- Bjorck: wtw = w^T w (verbatim R5, known-passing) --
__global__ void __launch_bounds__(256) syrk_kernel(int phase) {
    const float* W = phase ? (const float*)g_wb : (const float*)g_wa;
    int b = blockIdx.z;
    const float* A = W + (size_t)b * MATSZ;
    float* C = (float*)g_wtw + (size_t)b * MATSZ;
    __shared__ __align__(16) float As[16][64], Bs[16][64];
    int tid = threadIdx.x;
    int bk = tid >> 4, bi4 = (tid & 15) * 4;
    int tx = tid & 15, ty = tid >> 4;
    int I0 = blockIdx.y * 64, K0 = blockIdx.x * 64;
    float acc[4][4] = {};
    for (int j0 = 0; j0 < 256; j0 += 16) {
        *(float4*)&As[bk][bi4] = *(const float4*)&A[(j0 + bk) * 256 + I0 + bi4];
        *(float4*)&Bs[bk][bi4] = *(const float4*)&A[(j0 + bk) * 256 + K0 + bi4];
        __syncthreads();
#pragma unroll
        for (int kk = 0; kk < 16; kk++) {
            float4 a  = *(float4*)&As[kk][ty * 4];
            float4 bb = *(float4*)&Bs[kk][tx * 4];
            FMA16(a, bb);
        }
        __syncthreads();
    }
    store_tile(C, I0, K0, acc);
}

// ---------------- Bjorck: w' = 1.5 w - 0.5 w @ wtw (verbatim R5) ----
__global__ void __launch_bounds__(256) update_kernel(int phase) {
    const float* W = phase ? (const float*)g_wb : (const float*)g_wa;
    float* O       = phase ? (float*)g_wa       : (float*)g_wb;
    int b = blockIdx.z;
    const float* A = W + (size_t)b * MATSZ;
    const float* Bm = (const float*)g_wtw + (size_t)b * MATSZ;
    float* C = O + (size_t)b * MATSZ;
    __shared__ __align__(16) float As[16][64], Bs[16][64];
    int I0 = blockIdx.y * 64, K0 = blockIdx.x * 64;
    int tx = threadIdx.x & 15, ty = threadIdx.x >> 4;
    float acc[4][4] = {};
    gemm_nn_tile(A, Bm, I0, K0, 256, acc, As, Bs);
#pragma unroll
    for (int r = 0; r < 4; r++) {
        float4 wv = *(const float4*)&A[(I0 + ty * 4 + r) * 256 + K0 + tx * 4];
        float4 v;
        v.x = 1.5f * wv.x - 0.5f * acc[r][0];
        v.y = 1.5f * wv.y - 0.5f * acc[r][1];
        v.z = 1.5f * wv.z - 0.5f * acc[r][2];
        v.w = 1.5f * wv.w - 0.5f * acc[r][3];
        *(float4*)&C[(I0 + ty * 4 + r) * 256 + K0 + tx * 4] = v;
    }
}

// ---------------- PQ[m] = Mm Mm^T (sum over first 128 cols) --------
__global__ void pq_kernel() {
    int m = blockIdx.z;
    const float* A = (const float*)g_wa + (size_t)(1 + m) * MATSZ;
    float* C = (float*)g_PQ + (size_t)m * MATSZ;
    __shared__ __align__(16) float As[16][64], Bs[16][64];
    int I0 = blockIdx.y * 64, K0 = blockIdx.x * 64;
    float acc[4][4] = {};
    gemm_nt_tile(A, A, I0, K0, 128, acc, As, Bs);
    store_tile(C, I0, K0, acc);
}

// ---------------- C2[m] = PQ[2m] @ PQ[2m+1] -------------------------
__global__ void c2_kernel() {
    int m = blockIdx.z;
    const float* A = (const float*)g_PQ + (size_t)(2 * m) * MATSZ;
    const float* B = (const float*)g_PQ + (size_t)(2 * m + 1) * MATSZ;
    float* C = (float*)g_C2 + (size_t)m * MATSZ;
    __shared__ __align__(16) float As[16][64], Bs[16][64];
    int I0 = blockIdx.y * 64, K0 = blockIdx.x * 64;
    float acc[4][4] = {};
    gemm_nn_tile(A, B, I0, K0, 256, acc, As, Bs);
    store_tile(C, I0, K0, acc);
}

// blk[m] = {C, P1-C, P2-C, I-P1-P2+C}
__global__ void blk_kernel() {
    int e = blockIdx.x * 256 + threadIdx.x;
    int m = e >> 16, r = e & 65535;
    float C  = g_C2[m][r];
    float P1 = g_PQ[2 * m][r];
    float P2 = g_PQ[2 * m + 1][r];
    float I  = ((r >> 8) == (r & 255)) ? 1.0f : 0.0f;
    g_blk[m][0][r] = C;
    g_blk[m][1][r] = P1 - C;
    g_blk[m][2][r] = P2 - C;
    g_blk[m][3][r] = I - P1 - P2 + C;
}

// matrix_conv of two 2x2 block matrices -> 3x3
__global__ void mconv_kernel() {
    int z = blockIdx.z;
    int i = z / 3, j = z % 3;
    __shared__ __align__(16) float As[16][64], Bs[16][64];
    int I0 = blockIdx.y * 64, K0 = blockIdx.x * 64;
    float acc[4][4] = {};
    for (int i1 = 0; i1 < 2; i1++) {
        int di = i - i1;
        if (di < 0 || di > 1) continue;
        for (int j1 = 0; j1 < 2; j1++) {
            int dj = j - j1;
            if (dj < 0 || dj > 1) continue;
            const float* A = (const float*)g_blk + (size_t)(0 * 4 + i1 * 2 + j1) * MATSZ;
            const float* B = (const float*)g_blk + (size_t)(1 * 4 + di * 2 + dj) * MATSZ;
            gemm_nn_tile(A, B, I0, K0, 256, acc, As, Bs);
        }
    }
    store_tile((float*)g_p9 + (size_t)z * MATSZ, I0, K0, acc);
}

// W9[kh*3+kw][ic*256+oc] = (Hmat @ p[kw*3+kh])[ic][oc]
__global__ void tmat_kernel() {
    int z2 = blockIdx.z;
    int kh = z2 / 3, kw = z2 % 3;
    const float* A = (const float*)g_wa;         // ortho[0] = Hmat
    const float* B = (const float*)g_p9 + (size_t)(kw * 3 + kh) * MATSZ;
    float* C = (float*)g_W9 + (size_t)z2 * MATSZ;
    __shared__ __align__(16) float As[16][64], Bs[16][64];
    int I0 = blockIdx.y * 64, K0 = blockIdx.x * 64;
    float acc[4][4] = {};
    gemm_nn_tile(A, B, I0, K0, 256, acc, As, Bs);
    store_tile(C, I0, K0, acc);
}

// ---------------- the conv: 3x3, wrap pad, NCHW, packed f32x2 -------
// Per-output FMA sequence identical to the scalar R5 version (each
// output owns one fixed 32-bit lane of a 64-bit packed accumulator).
#define ICH 8
__global__ void __launch_bounds__(256) conv_kernel(const float* __restrict__ X,
                                                   const float* __restrict__ bias,
                                                   float* __restrict__ out) {
    __shared__ __align__(16) float Xs[ICH][4][68];   // [ic][row -1..+2][x -1..66]
    __shared__ __align__(16) float Ws2[ICH][9][128]; // [ic][tap][oc duplicated]
    int n = blockIdx.z;
    int Y0 = blockIdx.y * 2;
    int OC0 = blockIdx.x * 64;
    int tid = threadIdx.x;
    int tx = tid & 15;                     // oc group (4 oc)
    int py = tid >> 4;                     // pixel group
    int prow = py >> 3;                    // 0/1
    int xbase = (py & 7) * 8;              // 8 px per thread

    ull acc2[4][4];
#pragma unroll
    for (int pp = 0; pp < 4; pp++)
#pragma unroll
        for (int c = 0; c < 4; c++) acc2[pp][c] = 0ull;

    const float* Xn = X + (size_t)n * (256 * 4096);

    for (int ic0 = 0; ic0 < 256; ic0 += ICH) {
        for (int e = tid; e < ICH * 4 * 66; e += 256) {
            int ic = e / (4 * 66);
            int rr = (e / 66) % 4;
            int c  = e % 66;
            int gy = (Y0 - 1 + rr + 64) & 63;
            int gx = (c - 1 + 64) & 63;
            Xs[ic][rr][c] = Xn[(ic0 + ic) * 4096 + gy * 64 + gx];
        }
        for (int e = tid; e < ICH * 9 * 64; e += 256) {
            int ic = e / (9 * 64);
            int z  = (e / 64) % 9;
            int oc = e & 63;
            float w = g_W9[z][(ic0 + ic) * 256 + OC0 + oc];
            float2 wd; wd.x = w; wd.y = w;
            *(float2*)&Ws2[ic][z][2 * oc] = wd;
        }
        __syncthreads();

#pragma unroll 2
        for (int ic = 0; ic < ICH; ic++) {
#pragma unroll
            for (int dy = 0; dy < 3; dy++) {
                float4 v0 = *(float4*)&Xs[ic][prow + dy][xbase];
                float4 v1 = *(float4*)&Xs[ic][prow + dy][xbase + 4];
                float4 v2 = *(float4*)&Xs[ic][prow + dy][xbase + 8];
                float xf[12];
                xf[0] = v0.x; xf[1] = v0.y; xf[2]  = v0.z; xf[3]  = v0.w;
                xf[4] = v1.x; xf[5] = v1.y; xf[6]  = v1.z; xf[7]  = v1.w;
                xf[8] = v2.x; xf[9] = v2.y; xf[10] = v2.z; xf[11] = v2.w;
                ull pk[9];
#pragma unroll
                for (int s = 0; s < 9; s++) PACK2(pk[s], xf[s], xf[s + 1]);
#pragma unroll
                for (int dx = 0; dx < 3; dx++) {
                    int z = dy * 3 + dx;
                    ulonglong2 w01 = *(ulonglong2*)&Ws2[ic][z][tx * 8];
                    ulonglong2 w23 = *(ulonglong2*)&Ws2[ic][z][tx * 8 + 4];
#pragma unroll
                    for (int pp = 0; pp < 4; pp++) {
                        ull a = pk[2 * pp + dx];
                        FMA2(acc2[pp][0], a, w01.x);
                        FMA2(acc2[pp][1], a, w01.y);
                        FMA2(acc2[pp][2], a, w23.x);
                        FMA2(acc2[pp][3], a, w23.y);
                    }
                }
            }
        }
        __syncthreads();
    }

    float accf[8][4];
#pragma unroll
    for (int pp = 0; pp < 4; pp++)
#pragma unroll
        for (int c = 0; c < 4; c++) {
            float lo, hi;
            UNPACK2(lo, hi, acc2[pp][c]);
            accf[2 * pp][c] = lo;
            accf[2 * pp + 1][c] = hi;
        }

    float4 bv = *(const float4*)&bias[OC0 + tx * 4];
    int gy = Y0 + prow;
#pragma unroll
    for (int c = 0; c < 4; c++) {
        float bc = (c == 0) ? bv.x : (c == 1) ? bv.y : (c == 2) ? bv.z : bv.w;
        int oc = OC0 + tx * 4 + c;
        float* op = out + (((size_t)n * 256 + oc) * 64 + gy) * 64 + xbase;
        float4 o0, o1;
        o0.x = accf[0][c] + bc; o0.y = accf[1][c] + bc;
        o0.z = accf[2][c] + bc; o0.w = accf[3][c] + bc;
        o1.x = accf[4][c] + bc; o1.y = accf[5][c] + bc;
        o1.z = accf[6][c] + bc; o1.w = accf[7][c] + bc;
        *(float4*)&op[0] = o0;
        *(float4*)&op[4] = o1;
    }
}

// ------------------------------------------------------------------
extern "C" void kernel_launch(void* const* d_in, const int* in_sizes, int n_in,
                              void* d_out, int out_size) {
    const float *x = nullptr, *pm = nullptr, *bias = nullptr;
    for (int i = 0; i < n_in; i++) {
        if (in_sizes[i] == 16 * 256 * 64 * 64) x    = (const float*)d_in[i];
        else if (in_sizes[i] == 5 * 256 * 256) pm   = (const float*)d_in[i];
        else if (in_sizes[i] == 256)           bias = (const float*)d_in[i];
    }
    float* out = (float*)d_out;

    pi_kernel<<<5, 256>>>(pm);
    scale_kernel<<<1280, 256>>>(pm);
    for (int it = 0; it < 20; ++it) {
        syrk_kernel<<<dim3(4, 4, 5), 256>>>(it & 1);
        update_kernel<<<dim3(4, 4, 5), 256>>>(it & 1);
    }
    pq_kernel<<<dim3(4, 4, 4), 256>>>();
    c2_kernel<<<dim3(4, 4, 2), 256>>>();
    blk_kernel<<<512, 256>>>();
    mconv_kernel<<<dim3(4, 4, 9), 256>>>();
    tmat_kernel<<<dim3(4, 4, 9), 256>>>();
    conv_kernel<<<dim3(4, 32, 16), 256>>>(x, bias, out);
}

// round 11
// speedup vs baseline: 1.1881x; 1.1881x over previous
#include <cuda_runtime.h>
#include <math.h>

// ------------------------------------------------------------------
// B=16, C=256, H=W=64, K=3, 5 param matrices 256x256
// ------------------------------------------------------------------
#define MATSZ 65536  // 256*256

// ---------------- device scratch (no allocations) -----------------
__device__ float g_s[5];
__device__ float g_wa[5][MATSZ];
__device__ float g_wb[5][MATSZ];
__device__ float g_wtw[5][MATSZ];
__device__ float g_PQ[4][MATSZ];
__device__ float g_C2[2][MATSZ];
__device__ float g_blk[2][4][MATSZ];
__device__ float g_p9[9][MATSZ];
__device__ float g_W9[9][MATSZ];   // [kh*3+kw][ic*256+oc]

// ---------------- RNG: threefry2x32 (JAX partitionable) ------------
__device__ __forceinline__ unsigned rotl32(unsigned x, int d) {
    return (x << d) | (x >> (32 - d));
}

__device__ __forceinline__ void threefry2x32(unsigned k0, unsigned k1,
                                             unsigned& x0, unsigned& x1) {
    unsigned ks[3] = {k0, k1, k0 ^ k1 ^ 0x1BD11BDAu};
    const int r0[4] = {13, 15, 26, 6};
    const int r1[4] = {17, 29, 16, 24};
    x0 += ks[0]; x1 += ks[1];
#pragma unroll
    for (int i = 0; i < 5; i++) {
        const int* R = ((i & 1) == 0) ? r0 : r1;
#pragma unroll
        for (int j = 0; j < 4; j++) {
            x0 += x1;
            x1 = rotl32(x1, R[j]);
            x1 ^= x0;
        }
        x0 += ks[(i + 1) % 3];
        x1 += ks[(i + 2) % 3] + (unsigned)(i + 1);
    }
}

// XLA f32 erf_inv (Giles polynomial)
__device__ __forceinline__ float erfinv_f(float x) {
    float w = -log1pf(-x * x);
    float p;
    if (w < 5.0f) {
        w = w - 2.5f;
        p = 2.81022636e-08f;
        p = fmaf(p, w, 3.43273939e-07f);
        p = fmaf(p, w, -3.5233877e-06f);
        p = fmaf(p, w, -4.39150654e-06f);
        p = fmaf(p, w, 0.00021858087f);
        p = fmaf(p, w, -0.00125372503f);
        p = fmaf(p, w, -0.00417768164f);
        p = fmaf(p, w, 0.246640727f);
        p = fmaf(p, w, 1.50140941f);
    } else {
        w = sqrtf(w) - 3.0f;
        p = -0.000200214257f;
        p = fmaf(p, w, 0.000100950558f);
        p = fmaf(p, w, 0.00134934322f);
        p = fmaf(p, w, -0.00367342844f);
        p = fmaf(p, w, 0.00573950773f);
        p = fmaf(p, w, -0.0076224613f);
        p = fmaf(p, w, 0.00943887047f);
        p = fmaf(p, w, 1.00167406f);
        p = fmaf(p, w, 2.83297682f);
    }
    return p * x;
}

__device__ __forceinline__ float block_sum256(float v, float* red) {
    int t = threadIdx.x;
    red[t] = v;
    __syncthreads();
#pragma unroll
    for (int s = 128; s > 0; s >>= 1) {
        if (t < s) red[t] += red[t + s];
        __syncthreads();
    }
    float r = red[0];
    __syncthreads();
    return r;
}

// ---------------- kernel 1: RNG + power iteration ------------------
__global__ void pi_kernel(const float* __restrict__ pm) {
    __shared__ float su[256], sv[256], red[256];
    int b = blockIdx.x, t = threadIdx.x;

    unsigned idx = (unsigned)(b * 256 + t);     // 0..1279
    unsigned x0 = 0u, x1 = idx;
    threefry2x32(0u, 1u, x0, x1);
    unsigned bits = x1;                          // low word of 64-bit output
    float f = __uint_as_float((bits >> 9) | 0x3f800000u) - 1.0f;   // [0,1)
    const float lo = -0.99999994f;                                  // nextafter(-1,0)
    float val = fmaxf(lo, f * (1.0f - lo) + lo);
    su[t] = 1.41421354f * erfinv_f(val);
    __syncthreads();

    const float* A = pm + (size_t)b * MATSZ;
    float lastnorm = 1.0f;
    for (int it = 0; it < 10; it++) {
        float acc = 0.0f;
        for (int i = 0; i < 256; i++) acc = fmaf(A[i * 256 + t], su[i], acc);
        float nv = sqrtf(block_sum256(acc * acc, red));
        sv[t] = acc / nv;
        __syncthreads();
        float acc2 = 0.0f;
        for (int j = 0; j < 256; j++) acc2 = fmaf(A[t * 256 + j], sv[j], acc2);
        float nu = sqrtf(block_sum256(acc2 * acc2, red));
        su[t] = acc2 / nu;
        __syncthreads();
        lastnorm = nu;
    }
    if (t == 0) g_s[b] = lastnorm;
}

// w = pm / s[b]
__global__ void scale_kernel(const float* __restrict__ pm) {
    int i = blockIdx.x * 256 + threadIdx.x;
    ((float*)g_wa)[i] = pm[i] / g_s[i >> 16];
}

// ---------------- Bjorck: 32x32 tiles, 320 CTAs/launch --------------
// Same j-ascending reduction order per output as the 64x64 version ->
// bit-identical results, but 4x the CTA parallelism (fills the chip).

// wtw = w^T w : C[I0+i, K0+k] = sum_j A[j, I0+i] * A[j, K0+k]
__global__ void __launch_bounds__(256) syrk_kernel(int phase) {
    const float* W = phase ? (const float*)g_wb : (const float*)g_wa;
    int b = blockIdx.z;
    const float* A = W + (size_t)b * MATSZ;
    float* C = (float*)g_wtw + (size_t)b * MATSZ;
    __shared__ __align__(8) float As[16][32], Bs[16][32];
    int I0 = blockIdx.y * 32, K0 = blockIdx.x * 32;
    int tid = threadIdx.x;
    int jj = tid >> 4, ii2 = (tid & 15) * 2;
    int tx = tid & 15, ty = tid >> 4;
    float acc[2][2] = {};
    for (int j0 = 0; j0 < 256; j0 += 16) {
        *(float2*)&As[jj][ii2] = *(const float2*)&A[(j0 + jj) * 256 + I0 + ii2];
        *(float2*)&Bs[jj][ii2] = *(const float2*)&A[(j0 + jj) * 256 + K0 + ii2];
        __syncthreads();
#pragma unroll
        for (int kk = 0; kk < 16; kk++) {
            float2 a  = *(float2*)&As[kk][ty * 2];
            float2 bb = *(float2*)&Bs[kk][tx * 2];
            acc[0][0] = fmaf(a.x, bb.x, acc[0][0]);
            acc[0][1] = fmaf(a.x, bb.y, acc[0][1]);
            acc[1][0] = fmaf(a.y, bb.x, acc[1][0]);
            acc[1][1] = fmaf(a.y, bb.y, acc[1][1]);
        }
        __syncthreads();
    }
#pragma unroll
    for (int r = 0; r < 2; r++) {
        float2 v; v.x = acc[r][0]; v.y = acc[r][1];
        *(float2*)&C[(I0 + ty * 2 + r) * 256 + K0 + tx * 2] = v;
    }
}

// w' = 1.5 w - 0.5 * (w @ wtw)
__global__ void __launch_bounds__(256) update_kernel(int phase) {
    const float* W = phase ? (const float*)g_wb : (const float*)g_wa;
    float* O       = phase ? (float*)g_wa       : (float*)g_wb;
    int b = blockIdx.z;
    const float* A  = W + (size_t)b * MATSZ;
    const float* Bm = (const float*)g_wtw + (size_t)b * MATSZ;
    float* C = O + (size_t)b * MATSZ;
    __shared__ __align__(8) float As[16][32], Bs[16][32];
    int I0 = blockIdx.y * 32, K0 = blockIdx.x * 32;
    int tid = threadIdx.x;
    int jj = tid >> 4, kk2 = (tid & 15) * 2;     // Bs loader
    int ar = tid >> 3, ac2 = (tid & 7) * 2;      // As loader: row, 2 cols
    int tx = tid & 15, ty = tid >> 4;
    float acc[2][2] = {};
    for (int j0 = 0; j0 < 256; j0 += 16) {
        // As[col][row] = A[I0+row][j0+col], 32 rows x 16 cols, transposed
        float2 av = *(const float2*)&A[(I0 + ar) * 256 + j0 + ac2];
        As[ac2 + 0][ar] = av.x;
        As[ac2 + 1][ar] = av.y;
        *(float2*)&Bs[jj][kk2] = *(const float2*)&Bm[(j0 + jj) * 256 + K0 + kk2];
        __syncthreads();
#pragma unroll
        for (int kk = 0; kk < 16; kk++) {
            float2 a  = *(float2*)&As[kk][ty * 2];
            float2 bb = *(float2*)&Bs[kk][tx * 2];
            acc[0][0] = fmaf(a.x, bb.x, acc[0][0]);
            acc[0][1] = fmaf(a.x, bb.y, acc[0][1]);
            acc[1][0] = fmaf(a.y, bb.x, acc[1][0]);
            acc[1][1] = fmaf(a.y, bb.y, acc[1][1]);
        }
        __syncthreads();
    }
#pragma unroll
    for (int r = 0; r < 2; r++) {
        float2 wv = *(const float2*)&A[(I0 + ty * 2 + r) * 256 + K0 + tx * 2];
        float2 v;
        v.x = 1.5f * wv.x - 0.5f * acc[r][0];
        v.y = 1.5f * wv.y - 0.5f * acc[r][1];
        *(float2*)&C[(I0 + ty * 2 + r) * 256 + K0 + tx * 2] = v;
    }
}

// ---------------- plain tiled GEMM helpers (64x64, 256 thr) --------
#define FMA16(a, bb)                                                              \
    do {                                                                          \
        acc[0][0] = fmaf(a.x, bb.x, acc[0][0]); acc[0][1] = fmaf(a.x, bb.y, acc[0][1]); \
        acc[0][2] = fmaf(a.x, bb.z, acc[0][2]); acc[0][3] = fmaf(a.x, bb.w, acc[0][3]); \
        acc[1][0] = fmaf(a.y, bb.x, acc[1][0]); acc[1][1] = fmaf(a.y, bb.y, acc[1][1]); \
        acc[1][2] = fmaf(a.y, bb.z, acc[1][2]); acc[1][3] = fmaf(a.y, bb.w, acc[1][3]); \
        acc[2][0] = fmaf(a.z, bb.x, acc[2][0]); acc[2][1] = fmaf(a.z, bb.y, acc[2][1]); \
        acc[2][2] = fmaf(a.z, bb.z, acc[2][2]); acc[2][3] = fmaf(a.z, bb.w, acc[2][3]); \
        acc[3][0] = fmaf(a.w, bb.x, acc[3][0]); acc[3][1] = fmaf(a.w, bb.y, acc[3][1]); \
        acc[3][2] = fmaf(a.w, bb.z, acc[3][2]); acc[3][3] = fmaf(a.w, bb.w, acc[3][3]); \
    } while (0)

__device__ __forceinline__ void gemm_nn_tile(const float* __restrict__ A,
                                             const float* __restrict__ B,
                                             int I0, int K0, int Klen,
                                             float (&acc)[4][4],
                                             float (*As)[64], float (*Bs)[64]) {
    int tid = threadIdx.x;
    int lr = tid >> 2, lc4 = (tid & 3) * 4;
    int bk = tid >> 4, bi4 = (tid & 15) * 4;
    int tx = tid & 15, ty = tid >> 4;
    for (int j0 = 0; j0 < Klen; j0 += 16) {
        float4 av = *(const float4*)&A[(I0 + lr) * 256 + j0 + lc4];
        As[lc4 + 0][lr] = av.x; As[lc4 + 1][lr] = av.y;
        As[lc4 + 2][lr] = av.z; As[lc4 + 3][lr] = av.w;
        *(float4*)&Bs[bk][bi4] = *(const float4*)&B[(j0 + bk) * 256 + K0 + bi4];
        __syncthreads();
#pragma unroll
        for (int kk = 0; kk < 16; kk++) {
            float4 a  = *(float4*)&As[kk][ty * 4];
            float4 bb = *(float4*)&Bs[kk][tx * 4];
            FMA16(a, bb);
        }
        __syncthreads();
    }
}

__device__ __forceinline__ void gemm_nt_tile(const float* __restrict__ A,
                                             const float* __restrict__ B,
                                             int I0, int K0, int Klen,
                                             float (&acc)[4][4],
                                             float (*As)[64], float (*Bs)[64]) {
    int tid = threadIdx.x;
    int lr = tid >> 2, lc4 = (tid & 3) * 4;
    int tx = tid & 15, ty = tid >> 4;
    for (int j0 = 0; j0 < Klen; j0 += 16) {
        float4 av = *(const float4*)&A[(I0 + lr) * 256 + j0 + lc4];
        As[lc4 + 0][lr] = av.x; As[lc4 + 1][lr] = av.y;
        As[lc4 + 2][lr] = av.z; As[lc4 + 3][lr] = av.w;
        float4 bv = *(const float4*)&B[(K0 + lr) * 256 + j0 + lc4];
        Bs[lc4 + 0][lr] = bv.x; Bs[lc4 + 1][lr] = bv.y;
        Bs[lc4 + 2][lr] = bv.z; Bs[lc4 + 3][lr] = bv.w;
        __syncthreads();
#pragma unroll
        for (int kk = 0; kk < 16; kk++) {
            float4 a  = *(float4*)&As[kk][ty * 4];
            float4 bb = *(float4*)&Bs[kk][tx * 4];
            FMA16(a, bb);
        }
        __syncthreads();
    }
}

__device__ __forceinline__ void store_tile(float* __restrict__ C, int I0, int K0,
                                           float (&acc)[4][4]) {
    int tx = threadIdx.x & 15, ty = threadIdx.x >> 4;
#pragma unroll
    for (int r = 0; r < 4; r++) {
        float4 v;
        v.x = acc[r][0]; v.y = acc[r][1]; v.z = acc[r][2]; v.w = acc[r][3];
        *(float4*)&C[(I0 + ty * 4 + r) * 256 + K0 + tx * 4] = v;
    }
}

// ---------------- PQ[m] = Mm Mm^T (sum over first 128 cols) --------
__global__ void pq_kernel() {
    int m = blockIdx.z;
    const float* A = (const float*)g_wa + (size_t)(1 + m) * MATSZ;
    float* C = (float*)g_PQ + (size_t)m * MATSZ;
    __shared__ __align__(16) float As[16][64], Bs[16][64];
    int I0 = blockIdx.y * 64, K0 = blockIdx.x * 64;
    float acc[4][4] = {};
    gemm_nt_tile(A, A, I0, K0, 128, acc, As, Bs);
    store_tile(C, I0, K0, acc);
}

// ---------------- C2[m] = PQ[2m] @ PQ[2m+1] -------------------------
__global__ void c2_kernel() {
    int m = blockIdx.z;
    const float* A = (const float*)g_PQ + (size_t)(2 * m) * MATSZ;
    const float* B = (const float*)g_PQ + (size_t)(2 * m + 1) * MATSZ;
    float* C = (float*)g_C2 + (size_t)m * MATSZ;
    __shared__ __align__(16) float As[16][64], Bs[16][64];
    int I0 = blockIdx.y * 64, K0 = blockIdx.x * 64;
    float acc[4][4] = {};
    gemm_nn_tile(A, B, I0, K0, 256, acc, As, Bs);
    store_tile(C, I0, K0, acc);
}

// blk[m] = {C, P1-C, P2-C, I-P1-P2+C}
__global__ void blk_kernel() {
    int e = blockIdx.x * 256 + threadIdx.x;
    int m = e >> 16, r = e & 65535;
    float C  = g_C2[m][r];
    float P1 = g_PQ[2 * m][r];
    float P2 = g_PQ[2 * m + 1][r];
    float I  = ((r >> 8) == (r & 255)) ? 1.0f : 0.0f;
    g_blk[m][0][r] = C;
    g_blk[m][1][r] = P1 - C;
    g_blk[m][2][r] = P2 - C;
    g_blk[m][3][r] = I - P1 - P2 + C;
}

// matrix_conv of two 2x2 block matrices -> 3x3
__global__ void mconv_kernel() {
    int z = blockIdx.z;
    int i = z / 3, j = z % 3;
    __shared__ __align__(16) float As[16][64], Bs[16][64];
    int I0 = blockIdx.y * 64, K0 = blockIdx.x * 64;
    float acc[4][4] = {};
    for (int i1 = 0; i1 < 2; i1++) {
        int di = i - i1;
        if (di < 0 || di > 1) continue;
        for (int j1 = 0; j1 < 2; j1++) {
            int dj = j - j1;
            if (dj < 0 || dj > 1) continue;
            const float* A = (const float*)g_blk + (size_t)(0 * 4 + i1 * 2 + j1) * MATSZ;
            const float* B = (const float*)g_blk + (size_t)(1 * 4 + di * 2 + dj) * MATSZ;
            gemm_nn_tile(A, B, I0, K0, 256, acc, As, Bs);
        }
    }
    store_tile((float*)g_p9 + (size_t)z * MATSZ, I0, K0, acc);
}

// W9[kh*3+kw][ic*256+oc] = (Hmat @ p[kw*3+kh])[ic][oc]
__global__ void tmat_kernel() {
    int z2 = blockIdx.z;
    int kh = z2 / 3, kw = z2 % 3;
    const float* A = (const float*)g_wa;         // ortho[0] = Hmat
    const float* B = (const float*)g_p9 + (size_t)(kw * 3 + kh) * MATSZ;
    float* C = (float*)g_W9 + (size_t)z2 * MATSZ;
    __shared__ __align__(16) float As[16][64], Bs[16][64];
    int I0 = blockIdx.y * 64, K0 = blockIdx.x * 64;
    float acc[4][4] = {};
    gemm_nn_tile(A, B, I0, K0, 256, acc, As, Bs);
    store_tile(C, I0, K0, acc);
}

// ---------------- the conv: 3x3, wrap pad, NCHW (scalar, R5) --------
#define ICH 8
__global__ void __launch_bounds__(256) conv_kernel(const float* __restrict__ X,
                                                   const float* __restrict__ bias,
                                                   float* __restrict__ out) {
    __shared__ __align__(16) float Xs[ICH][4][68];
    __shared__ __align__(16) float Ws[ICH][9][64];
    int n = blockIdx.z;
    int Y0 = blockIdx.y * 2;
    int OC0 = blockIdx.x * 64;
    int tid = threadIdx.x;
    int tx = tid & 15;
    int py = tid >> 4;
    int prow = py >> 3;
    int xbase = (py & 7) * 8;

    float acc[8][4] = {};
    const float* Xn = X + (size_t)n * (256 * 4096);

    for (int ic0 = 0; ic0 < 256; ic0 += ICH) {
        for (int e = tid; e < ICH * 4 * 66; e += 256) {
            int ic = e / (4 * 66);
            int rr = (e / 66) % 4;
            int c  = e % 66;
            int gy = (Y0 - 1 + rr + 64) & 63;
            int gx = (c - 1 + 64) & 63;
            Xs[ic][rr][c] = Xn[(ic0 + ic) * 4096 + gy * 64 + gx];
        }
        for (int e = tid; e < ICH * 9 * 64; e += 256) {
            int ic = e / (9 * 64);
            int z  = (e / 64) % 9;
            int oc = e & 63;
            Ws[ic][z][oc] = g_W9[z][(ic0 + ic) * 256 + OC0 + oc];
        }
        __syncthreads();

#pragma unroll 2
        for (int ic = 0; ic < ICH; ic++) {
            float xr[3][12];
#pragma unroll
            for (int q = 0; q < 3; q++) {
                float4 v0 = *(float4*)&Xs[ic][prow + q][xbase];
                float4 v1 = *(float4*)&Xs[ic][prow + q][xbase + 4];
                float4 v2 = *(float4*)&Xs[ic][prow + q][xbase + 8];
                xr[q][0] = v0.x; xr[q][1] = v0.y; xr[q][2]  = v0.z; xr[q][3]  = v0.w;
                xr[q][4] = v1.x; xr[q][5] = v1.y; xr[q][6]  = v1.z; xr[q][7]  = v1.w;
                xr[q][8] = v2.x; xr[q][9] = v2.y; xr[q][10] = v2.z; xr[q][11] = v2.w;
            }
#pragma unroll
            for (int dy = 0; dy < 3; dy++) {
#pragma unroll
                for (int dx = 0; dx < 3; dx++) {
                    float4 w4 = *(float4*)&Ws[ic][dy * 3 + dx][tx * 4];
#pragma unroll
                    for (int p = 0; p < 8; p++) {
                        float a = xr[dy][p + dx];
                        acc[p][0] = fmaf(a, w4.x, acc[p][0]);
                        acc[p][1] = fmaf(a, w4.y, acc[p][1]);
                        acc[p][2] = fmaf(a, w4.z, acc[p][2]);
                        acc[p][3] = fmaf(a, w4.w, acc[p][3]);
                    }
                }
            }
        }
        __syncthreads();
    }

    float4 bv = *(const float4*)&bias[OC0 + tx * 4];
    int gy = Y0 + prow;
#pragma unroll
    for (int c = 0; c < 4; c++) {
        float bc = (c == 0) ? bv.x : (c == 1) ? bv.y : (c == 2) ? bv.z : bv.w;
        int oc = OC0 + tx * 4 + c;
        float* op = out + (((size_t)n * 256 + oc) * 64 + gy) * 64 + xbase;
        float4 o0, o1;
        o0.x = acc[0][c] + bc; o0.y = acc[1][c] + bc;
        o0.z = acc[2][c] + bc; o0.w = acc[3][c] + bc;
        o1.x = acc[4][c] + bc; o1.y = acc[5][c] + bc;
        o1.z = acc[6][c] + bc; o1.w = acc[7][c] + bc;
        *(float4*)&op[0] = o0;
        *(float4*)&op[4] = o1;
    }
}

// ------------------------------------------------------------------
extern "C" void kernel_launch(void* const* d_in, const int* in_sizes, int n_in,
                              void* d_out, int out_size) {
    const float *x = nullptr, *pm = nullptr, *bias = nullptr;
    for (int i = 0; i < n_in; i++) {
        if (in_sizes[i] == 16 * 256 * 64 * 64) x    = (const float*)d_in[i];
        else if (in_sizes[i] == 5 * 256 * 256) pm   = (const float*)d_in[i];
        else if (in_sizes[i] == 256)           bias = (const float*)d_in[i];
    }
    float* out = (float*)d_out;

    pi_kernel<<<5, 256>>>(pm);
    scale_kernel<<<1280, 256>>>(pm);
    for (int it = 0; it < 20; ++it) {
        syrk_kernel<<<dim3(8, 8, 5), 256>>>(it & 1);
        update_kernel<<<dim3(8, 8, 5), 256>>>(it & 1);
    }
    pq_kernel<<<dim3(4, 4, 4), 256>>>();
    c2_kernel<<<dim3(4, 4, 2), 256>>>();
    blk_kernel<<<512, 256>>>();
    mconv_kernel<<<dim3(4, 4, 9), 256>>>();
    tmat_kernel<<<dim3(4, 4, 9), 256>>>();
    conv_kernel<<<dim3(4, 32, 16), 256>>>(x, bias, out);
}

// round 12
// speedup vs baseline: 1.1885x; 1.0004x over previous
#include <cuda_runtime.h>
#include <math.h>

// ------------------------------------------------------------------
// B=16, C=256, H=W=64, K=3, 5 param matrices 256x256
// ------------------------------------------------------------------
#define MATSZ 65536  // 256*256

// ---------------- device scratch (no allocations) -----------------
__device__ float g_s[5];
__device__ float g_wa[5][MATSZ];
__device__ float g_wb[5][MATSZ];
__device__ float g_wtw[5][MATSZ];
__device__ float g_PQ[4][MATSZ];
__device__ float g_C2[2][MATSZ];
__device__ float g_blk[2][4][MATSZ];
__device__ float g_p9[9][MATSZ];
__device__ float g_W9[9][MATSZ];   // [kh*3+kw][ic*256+oc]

// ---------------- RNG: threefry2x32 (JAX partitionable) ------------
__device__ __forceinline__ unsigned rotl32(unsigned x, int d) {
    return (x << d) | (x >> (32 - d));
}

__device__ __forceinline__ void threefry2x32(unsigned k0, unsigned k1,
                                             unsigned& x0, unsigned& x1) {
    unsigned ks[3] = {k0, k1, k0 ^ k1 ^ 0x1BD11BDAu};
    const int r0[4] = {13, 15, 26, 6};
    const int r1[4] = {17, 29, 16, 24};
    x0 += ks[0]; x1 += ks[1];
#pragma unroll
    for (int i = 0; i < 5; i++) {
        const int* R = ((i & 1) == 0) ? r0 : r1;
#pragma unroll
        for (int j = 0; j < 4; j++) {
            x0 += x1;
            x1 = rotl32(x1, R[j]);
            x1 ^= x0;
        }
        x0 += ks[(i + 1) % 3];
        x1 += ks[(i + 2) % 3] + (unsigned)(i + 1);
    }
}

// XLA f32 erf_inv (Giles polynomial)
__device__ __forceinline__ float erfinv_f(float x) {
    float w = -log1pf(-x * x);
    float p;
    if (w < 5.0f) {
        w = w - 2.5f;
        p = 2.81022636e-08f;
        p = fmaf(p, w, 3.43273939e-07f);
        p = fmaf(p, w, -3.5233877e-06f);
        p = fmaf(p, w, -4.39150654e-06f);
        p = fmaf(p, w, 0.00021858087f);
        p = fmaf(p, w, -0.00125372503f);
        p = fmaf(p, w, -0.00417768164f);
        p = fmaf(p, w, 0.246640727f);
        p = fmaf(p, w, 1.50140941f);
    } else {
        w = sqrtf(w) - 3.0f;
        p = -0.000200214257f;
        p = fmaf(p, w, 0.000100950558f);
        p = fmaf(p, w, 0.00134934322f);
        p = fmaf(p, w, -0.00367342844f);
        p = fmaf(p, w, 0.00573950773f);
        p = fmaf(p, w, -0.0076224613f);
        p = fmaf(p, w, 0.00943887047f);
        p = fmaf(p, w, 1.00167406f);
        p = fmaf(p, w, 2.83297682f);
    }
    return p * x;
}

__device__ __forceinline__ float block_sum256(float v, float* red) {
    int t = threadIdx.x;
    red[t] = v;
    __syncthreads();
#pragma unroll
    for (int s = 128; s > 0; s >>= 1) {
        if (t < s) red[t] += red[t + s];
        __syncthreads();
    }
    float r = red[0];
    __syncthreads();
    return r;
}

// ---------------- kernel 1: RNG + power iteration ------------------
__global__ void pi_kernel(const float* __restrict__ pm) {
    __shared__ float su[256], sv[256], red[256];
    int b = blockIdx.x, t = threadIdx.x;

    unsigned idx = (unsigned)(b * 256 + t);     // 0..1279
    unsigned x0 = 0u, x1 = idx;
    threefry2x32(0u, 1u, x0, x1);
    unsigned bits = x1;                          // low word of 64-bit output
    float f = __uint_as_float((bits >> 9) | 0x3f800000u) - 1.0f;   // [0,1)
    const float lo = -0.99999994f;                                  // nextafter(-1,0)
    float val = fmaxf(lo, f * (1.0f - lo) + lo);
    su[t] = 1.41421354f * erfinv_f(val);
    __syncthreads();

    const float* A = pm + (size_t)b * MATSZ;
    float lastnorm = 1.0f;
    for (int it = 0; it < 10; it++) {
        float acc = 0.0f;
        for (int i = 0; i < 256; i++) acc = fmaf(A[i * 256 + t], su[i], acc);
        float nv = sqrtf(block_sum256(acc * acc, red));
        sv[t] = acc / nv;
        __syncthreads();
        float acc2 = 0.0f;
        for (int j = 0; j < 256; j++) acc2 = fmaf(A[t * 256 + j], sv[j], acc2);
        float nu = sqrtf(block_sum256(acc2 * acc2, red));
        su[t] = acc2 / nu;
        __syncthreads();
        lastnorm = nu;
    }
    if (t == 0) g_s[b] = lastnorm;
}

// w = pm / s[b]
__global__ void scale_kernel(const float* __restrict__ pm) {
    int i = blockIdx.x * 256 + threadIdx.x;
    ((float*)g_wa)[i] = pm[i] / g_s[i >> 16];
}

// ---------------- Bjorck: 32x32 tiles, 320 CTAs/launch --------------
// Same j-ascending reduction order per output as the 64x64 version ->
// bit-identical results, but 4x the CTA parallelism (fills the chip).

// wtw = w^T w : C[I0+i, K0+k] = sum_j A[j, I0+i] * A[j, K0+k]
__global__ void __launch_bounds__(256) syrk_kernel(int phase) {
    const float* W = phase ? (const float*)g_wb : (const float*)g_wa;
    int b = blockIdx.z;
    const float* A = W + (size_t)b * MATSZ;
    float* C = (float*)g_wtw + (size_t)b * MATSZ;
    __shared__ __align__(8) float As[16][32], Bs[16][32];
    int I0 = blockIdx.y * 32, K0 = blockIdx.x * 32;
    int tid = threadIdx.x;
    int jj = tid >> 4, ii2 = (tid & 15) * 2;
    int tx = tid & 15, ty = tid >> 4;
    float acc[2][2] = {};
    for (int j0 = 0; j0 < 256; j0 += 16) {
        *(float2*)&As[jj][ii2] = *(const float2*)&A[(j0 + jj) * 256 + I0 + ii2];
        *(float2*)&Bs[jj][ii2] = *(const float2*)&A[(j0 + jj) * 256 + K0 + ii2];
        __syncthreads();
#pragma unroll
        for (int kk = 0; kk < 16; kk++) {
            float2 a  = *(float2*)&As[kk][ty * 2];
            float2 bb = *(float2*)&Bs[kk][tx * 2];
            acc[0][0] = fmaf(a.x, bb.x, acc[0][0]);
            acc[0][1] = fmaf(a.x, bb.y, acc[0][1]);
            acc[1][0] = fmaf(a.y, bb.x, acc[1][0]);
            acc[1][1] = fmaf(a.y, bb.y, acc[1][1]);
        }
        __syncthreads();
    }
#pragma unroll
    for (int r = 0; r < 2; r++) {
        float2 v; v.x = acc[r][0]; v.y = acc[r][1];
        *(float2*)&C[(I0 + ty * 2 + r) * 256 + K0 + tx * 2] = v;
    }
}

// w' = 1.5 w - 0.5 * (w @ wtw)
__global__ void __launch_bounds__(256) update_kernel(int phase) {
    const float* W = phase ? (const float*)g_wb : (const float*)g_wa;
    float* O       = phase ? (float*)g_wa       : (float*)g_wb;
    int b = blockIdx.z;
    const float* A  = W + (size_t)b * MATSZ;
    const float* Bm = (const float*)g_wtw + (size_t)b * MATSZ;
    float* C = O + (size_t)b * MATSZ;
    __shared__ __align__(8) float As[16][32], Bs[16][32];
    int I0 = blockIdx.y * 32, K0 = blockIdx.x * 32;
    int tid = threadIdx.x;
    int jj = tid >> 4, kk2 = (tid & 15) * 2;     // Bs loader
    int ar = tid >> 3, ac2 = (tid & 7) * 2;      // As loader: row, 2 cols
    int tx = tid & 15, ty = tid >> 4;
    float acc[2][2] = {};
    for (int j0 = 0; j0 < 256; j0 += 16) {
        // As[col][row] = A[I0+row][j0+col], 32 rows x 16 cols, transposed
        float2 av = *(const float2*)&A[(I0 + ar) * 256 + j0 + ac2];
        As[ac2 + 0][ar] = av.x;
        As[ac2 + 1][ar] = av.y;
        *(float2*)&Bs[jj][kk2] = *(const float2*)&Bm[(j0 + jj) * 256 + K0 + kk2];
        __syncthreads();
#pragma unroll
        for (int kk = 0; kk < 16; kk++) {
            float2 a  = *(float2*)&As[kk][ty * 2];
            float2 bb = *(float2*)&Bs[kk][tx * 2];
            acc[0][0] = fmaf(a.x, bb.x, acc[0][0]);
            acc[0][1] = fmaf(a.x, bb.y, acc[0][1]);
            acc[1][0] = fmaf(a.y, bb.x, acc[1][0]);
            acc[1][1] = fmaf(a.y, bb.y, acc[1][1]);
        }
        __syncthreads();
    }
#pragma unroll
    for (int r = 0; r < 2; r++) {
        float2 wv = *(const float2*)&A[(I0 + ty * 2 + r) * 256 + K0 + tx * 2];
        float2 v;
        v.x = 1.5f * wv.x - 0.5f * acc[r][0];
        v.y = 1.5f * wv.y - 0.5f * acc[r][1];
        *(float2*)&C[(I0 + ty * 2 + r) * 256 + K0 + tx * 2] = v;
    }
}

// ---------------- plain tiled GEMM helpers (64x64, 256 thr) --------
#define FMA16(a, bb)                                                              \
    do {                                                                          \
        acc[0][0] = fmaf(a.x, bb.x, acc[0][0]); acc[0][1] = fmaf(a.x, bb.y, acc[0][1]); \
        acc[0][2] = fmaf(a.x, bb.z, acc[0][2]); acc[0][3] = fmaf(a.x, bb.w, acc[0][3]); \
        acc[1][0] = fmaf(a.y, bb.x, acc[1][0]); acc[1][1] = fmaf(a.y, bb.y, acc[1][1]); \
        acc[1][2] = fmaf(a.y, bb.z, acc[1][2]); acc[1][3] = fmaf(a.y, bb.w, acc[1][3]); \
        acc[2][0] = fmaf(a.z, bb.x, acc[2][0]); acc[2][1] = fmaf(a.z, bb.y, acc[2][1]); \
        acc[2][2] = fmaf(a.z, bb.z, acc[2][2]); acc[2][3] = fmaf(a.z, bb.w, acc[2][3]); \
        acc[3][0] = fmaf(a.w, bb.x, acc[3][0]); acc[3][1] = fmaf(a.w, bb.y, acc[3][1]); \
        acc[3][2] = fmaf(a.w, bb.z, acc[3][2]); acc[3][3] = fmaf(a.w, bb.w, acc[3][3]); \
    } while (0)

__device__ __forceinline__ void gemm_nn_tile(const float* __restrict__ A,
                                             const float* __restrict__ B,
                                             int I0, int K0, int Klen,
                                             float (&acc)[4][4],
                                             float (*As)[64], float (*Bs)[64]) {
    int tid = threadIdx.x;
    int lr = tid >> 2, lc4 = (tid & 3) * 4;
    int bk = tid >> 4, bi4 = (tid & 15) * 4;
    int tx = tid & 15, ty = tid >> 4;
    for (int j0 = 0; j0 < Klen; j0 += 16) {
        float4 av = *(const float4*)&A[(I0 + lr) * 256 + j0 + lc4];
        As[lc4 + 0][lr] = av.x; As[lc4 + 1][lr] = av.y;
        As[lc4 + 2][lr] = av.z; As[lc4 + 3][lr] = av.w;
        *(float4*)&Bs[bk][bi4] = *(const float4*)&B[(j0 + bk) * 256 + K0 + bi4];
        __syncthreads();
#pragma unroll
        for (int kk = 0; kk < 16; kk++) {
            float4 a  = *(float4*)&As[kk][ty * 4];
            float4 bb = *(float4*)&Bs[kk][tx * 4];
            FMA16(a, bb);
        }
        __syncthreads();
    }
}

__device__ __forceinline__ void gemm_nt_tile(const float* __restrict__ A,
                                             const float* __restrict__ B,
                                             int I0, int K0, int Klen,
                                             float (&acc)[4][4],
                                             float (*As)[64], float (*Bs)[64]) {
    int tid = threadIdx.x;
    int lr = tid >> 2, lc4 = (tid & 3) * 4;
    int tx = tid & 15, ty = tid >> 4;
    for (int j0 = 0; j0 < Klen; j0 += 16) {
        float4 av = *(const float4*)&A[(I0 + lr) * 256 + j0 + lc4];
        As[lc4 + 0][lr] = av.x; As[lc4 + 1][lr] = av.y;
        As[lc4 + 2][lr] = av.z; As[lc4 + 3][lr] = av.w;
        float4 bv = *(const float4*)&B[(K0 + lr) * 256 + j0 + lc4];
        Bs[lc4 + 0][lr] = bv.x; Bs[lc4 + 1][lr] = bv.y;
        Bs[lc4 + 2][lr] = bv.z; Bs[lc4 + 3][lr] = bv.w;
        __syncthreads();
#pragma unroll
        for (int kk = 0; kk < 16; kk++) {
            float4 a  = *(float4*)&As[kk][ty * 4];
            float4 bb = *(float4*)&Bs[kk][tx * 4];
            FMA16(a, bb);
        }
        __syncthreads();
    }
}

__device__ __forceinline__ void store_tile(float* __restrict__ C, int I0, int K0,
                                           float (&acc)[4][4]) {
    int tx = threadIdx.x & 15, ty = threadIdx.x >> 4;
#pragma unroll
    for (int r = 0; r < 4; r++) {
        float4 v;
        v.x = acc[r][0]; v.y = acc[r][1]; v.z = acc[r][2]; v.w = acc[r][3];
        *(float4*)&C[(I0 + ty * 4 + r) * 256 + K0 + tx * 4] = v;
    }
}

// ---------------- PQ[m] = Mm Mm^T (sum over first 128 cols) --------
__global__ void pq_kernel() {
    int m = blockIdx.z;
    const float* A = (const float*)g_wa + (size_t)(1 + m) * MATSZ;
    float* C = (float*)g_PQ + (size_t)m * MATSZ;
    __shared__ __align__(16) float As[16][64], Bs[16][64];
    int I0 = blockIdx.y * 64, K0 = blockIdx.x * 64;
    float acc[4][4] = {};
    gemm_nt_tile(A, A, I0, K0, 128, acc, As, Bs);
    store_tile(C, I0, K0, acc);
}

// ---------------- C2[m] = PQ[2m] @ PQ[2m+1] -------------------------
__global__ void c2_kernel() {
    int m = blockIdx.z;
    const float* A = (const float*)g_PQ + (size_t)(2 * m) * MATSZ;
    const float* B = (const float*)g_PQ + (size_t)(2 * m + 1) * MATSZ;
    float* C = (float*)g_C2 + (size_t)m * MATSZ;
    __shared__ __align__(16) float As[16][64], Bs[16][64];
    int I0 = blockIdx.y * 64, K0 = blockIdx.x * 64;
    float acc[4][4] = {};
    gemm_nn_tile(A, B, I0, K0, 256, acc, As, Bs);
    store_tile(C, I0, K0, acc);
}

// blk[m] = {C, P1-C, P2-C, I-P1-P2+C}
__global__ void blk_kernel() {
    int e = blockIdx.x * 256 + threadIdx.x;
    int m = e >> 16, r = e & 65535;
    float C  = g_C2[m][r];
    float P1 = g_PQ[2 * m][r];
    float P2 = g_PQ[2 * m + 1][r];
    float I  = ((r >> 8) == (r & 255)) ? 1.0f : 0.0f;
    g_blk[m][0][r] = C;
    g_blk[m][1][r] = P1 - C;
    g_blk[m][2][r] = P2 - C;
    g_blk[m][3][r] = I - P1 - P2 + C;
}

// matrix_conv of two 2x2 block matrices -> 3x3
__global__ void mconv_kernel() {
    int z = blockIdx.z;
    int i = z / 3, j = z % 3;
    __shared__ __align__(16) float As[16][64], Bs[16][64];
    int I0 = blockIdx.y * 64, K0 = blockIdx.x * 64;
    float acc[4][4] = {};
    for (int i1 = 0; i1 < 2; i1++) {
        int di = i - i1;
        if (di < 0 || di > 1) continue;
        for (int j1 = 0; j1 < 2; j1++) {
            int dj = j - j1;
            if (dj < 0 || dj > 1) continue;
            const float* A = (const float*)g_blk + (size_t)(0 * 4 + i1 * 2 + j1) * MATSZ;
            const float* B = (const float*)g_blk + (size_t)(1 * 4 + di * 2 + dj) * MATSZ;
            gemm_nn_tile(A, B, I0, K0, 256, acc, As, Bs);
        }
    }
    store_tile((float*)g_p9 + (size_t)z * MATSZ, I0, K0, acc);
}

// W9[kh*3+kw][ic*256+oc] = (Hmat @ p[kw*3+kh])[ic][oc]
__global__ void tmat_kernel() {
    int z2 = blockIdx.z;
    int kh = z2 / 3, kw = z2 % 3;
    const float* A = (const float*)g_wa;         // ortho[0] = Hmat
    const float* B = (const float*)g_p9 + (size_t)(kw * 3 + kh) * MATSZ;
    float* C = (float*)g_W9 + (size_t)z2 * MATSZ;
    __shared__ __align__(16) float As[16][64], Bs[16][64];
    int I0 = blockIdx.y * 64, K0 = blockIdx.x * 64;
    float acc[4][4] = {};
    gemm_nn_tile(A, B, I0, K0, 256, acc, As, Bs);
    store_tile(C, I0, K0, acc);
}

// ---------------- the conv: 3x3, wrap pad, NCHW (scalar, R5) --------
#define ICH 8
__global__ void __launch_bounds__(256) conv_kernel(const float* __restrict__ X,
                                                   const float* __restrict__ bias,
                                                   float* __restrict__ out) {
    __shared__ __align__(16) float Xs[ICH][4][68];
    __shared__ __align__(16) float Ws[ICH][9][64];
    int n = blockIdx.z;
    int Y0 = blockIdx.y * 2;
    int OC0 = blockIdx.x * 64;
    int tid = threadIdx.x;
    int tx = tid & 15;
    int py = tid >> 4;
    int prow = py >> 3;
    int xbase = (py & 7) * 8;

    float acc[8][4] = {};
    const float* Xn = X + (size_t)n * (256 * 4096);

    for (int ic0 = 0; ic0 < 256; ic0 += ICH) {
        for (int e = tid; e < ICH * 4 * 66; e += 256) {
            int ic = e / (4 * 66);
            int rr = (e / 66) % 4;
            int c  = e % 66;
            int gy = (Y0 - 1 + rr + 64) & 63;
            int gx = (c - 1 + 64) & 63;
            Xs[ic][rr][c] = Xn[(ic0 + ic) * 4096 + gy * 64 + gx];
        }
        for (int e = tid; e < ICH * 9 * 64; e += 256) {
            int ic = e / (9 * 64);
            int z  = (e / 64) % 9;
            int oc = e & 63;
            Ws[ic][z][oc] = g_W9[z][(ic0 + ic) * 256 + OC0 + oc];
        }
        __syncthreads();

#pragma unroll 2
        for (int ic = 0; ic < ICH; ic++) {
            float xr[3][12];
#pragma unroll
            for (int q = 0; q < 3; q++) {
                float4 v0 = *(float4*)&Xs[ic][prow + q][xbase];
                float4 v1 = *(float4*)&Xs[ic][prow + q][xbase + 4];
                float4 v2 = *(float4*)&Xs[ic][prow + q][xbase + 8];
                xr[q][0] = v0.x; xr[q][1] = v0.y; xr[q][2]  = v0.z; xr[q][3]  = v0.w;
                xr[q][4] = v1.x; xr[q][5] = v1.y; xr[q][6]  = v1.z; xr[q][7]  = v1.w;
                xr[q][8] = v2.x; xr[q][9] = v2.y; xr[q][10] = v2.z; xr[q][11] = v2.w;
            }
#pragma unroll
            for (int dy = 0; dy < 3; dy++) {
#pragma unroll
                for (int dx = 0; dx < 3; dx++) {
                    float4 w4 = *(float4*)&Ws[ic][dy * 3 + dx][tx * 4];
#pragma unroll
                    for (int p = 0; p < 8; p++) {
                        float a = xr[dy][p + dx];
                        acc[p][0] = fmaf(a, w4.x, acc[p][0]);
                        acc[p][1] = fmaf(a, w4.y, acc[p][1]);
                        acc[p][2] = fmaf(a, w4.z, acc[p][2]);
                        acc[p][3] = fmaf(a, w4.w, acc[p][3]);
                    }
                }
            }
        }
        __syncthreads();
    }

    float4 bv = *(const float4*)&bias[OC0 + tx * 4];
    int gy = Y0 + prow;
#pragma unroll
    for (int c = 0; c < 4; c++) {
        float bc = (c == 0) ? bv.x : (c == 1) ? bv.y : (c == 2) ? bv.z : bv.w;
        int oc = OC0 + tx * 4 + c;
        float* op = out + (((size_t)n * 256 + oc) * 64 + gy) * 64 + xbase;
        float4 o0, o1;
        o0.x = acc[0][c] + bc; o0.y = acc[1][c] + bc;
        o0.z = acc[2][c] + bc; o0.w = acc[3][c] + bc;
        o1.x = acc[4][c] + bc; o1.y = acc[5][c] + bc;
        o1.z = acc[6][c] + bc; o1.w = acc[7][c] + bc;
        *(float4*)&op[0] = o0;
        *(float4*)&op[4] = o1;
    }
}

// ------------------------------------------------------------------
extern "C" void kernel_launch(void* const* d_in, const int* in_sizes, int n_in,
                              void* d_out, int out_size) {
    const float *x = nullptr, *pm = nullptr, *bias = nullptr;
    for (int i = 0; i < n_in; i++) {
        if (in_sizes[i] == 16 * 256 * 64 * 64) x    = (const float*)d_in[i];
        else if (in_sizes[i] == 5 * 256 * 256) pm   = (const float*)d_in[i];
        else if (in_sizes[i] == 256)           bias = (const float*)d_in[i];
    }
    float* out = (float*)d_out;

    pi_kernel<<<5, 256>>>(pm);
    scale_kernel<<<1280, 256>>>(pm);
    for (int it = 0; it < 20; ++it) {
        syrk_kernel<<<dim3(8, 8, 5), 256>>>(it & 1);
        update_kernel<<<dim3(8, 8, 5), 256>>>(it & 1);
    }
    pq_kernel<<<dim3(4, 4, 4), 256>>>();
    c2_kernel<<<dim3(4, 4, 2), 256>>>();
    blk_kernel<<<512, 256>>>();
    mconv_kernel<<<dim3(4, 4, 9), 256>>>();
    tmat_kernel<<<dim3(4, 4, 9), 256>>>();
    conv_kernel<<<dim3(4, 32, 16), 256>>>(x, bias, out);
}

// round 15
// speedup vs baseline: 1.6987x; 1.4293x over previous
#include <cuda_runtime.h>
#include <cuda_bf16.h>
#include <mma.h>
#include <cstdint>
#include <math.h>
using namespace nvcuda;

#define MATSZ 65536

__device__ float g_s[5];
__device__ float g_wa[5][MATSZ];
__device__ float g_wb[5][MATSZ];
__device__ float g_wtw[5][MATSZ];
__device__ float g_PQ[4][MATSZ];
__device__ float g_C2[2][MATSZ];
__device__ float g_blk[2][4][MATSZ];
__device__ float g_p9[9][MATSZ];
__device__ float g_W9[9][MATSZ];
__device__ unsigned short g_Xhi[(size_t)16*64*64*256];   // [n][y][x][ic]
__device__ unsigned short g_Xlo[(size_t)16*64*64*256];
__device__ unsigned short g_Whi[9*256*256];              // [z][oc][ic]
__device__ unsigned short g_Wlo[9*256*256];

// ---------- RNG ----------
__device__ __forceinline__ unsigned rotl32(unsigned x,int d){return (x<<d)|(x>>(32-d));}
__device__ __forceinline__ void threefry2x32(unsigned k0,unsigned k1,unsigned&x0,unsigned&x1){
    unsigned ks[3]={k0,k1,k0^k1^0x1BD11BDAu};
    const int r0[4]={13,15,26,6}, r1[4]={17,29,16,24};
    x0+=ks[0]; x1+=ks[1];
#pragma unroll
    for(int i=0;i<5;i++){ const int*R=((i&1)==0)?r0:r1;
#pragma unroll
        for(int j=0;j<4;j++){ x0+=x1; x1=rotl32(x1,R[j]); x1^=x0; }
        x0+=ks[(i+1)%3]; x1+=ks[(i+2)%3]+(unsigned)(i+1); }
}
__device__ __forceinline__ float erfinv_f(float x){
    float w=-log1pf(-x*x), p;
    if(w<5.0f){ w-=2.5f; p=2.81022636e-08f; p=fmaf(p,w,3.43273939e-07f); p=fmaf(p,w,-3.5233877e-06f);
        p=fmaf(p,w,-4.39150654e-06f); p=fmaf(p,w,0.00021858087f); p=fmaf(p,w,-0.00125372503f);
        p=fmaf(p,w,-0.00417768164f); p=fmaf(p,w,0.246640727f); p=fmaf(p,w,1.50140941f);
    } else { w=sqrtf(w)-3.0f; p=-0.000200214257f; p=fmaf(p,w,0.000100950558f); p=fmaf(p,w,0.00134934322f);
        p=fmaf(p,w,-0.00367342844f); p=fmaf(p,w,0.00573950773f); p=fmaf(p,w,-0.0076224613f);
        p=fmaf(p,w,0.00943887047f); p=fmaf(p,w,1.00167406f); p=fmaf(p,w,2.83297682f); }
    return p*x;
}
__device__ __forceinline__ float block_sum256(float v,float*red){
    int t=threadIdx.x; red[t]=v; __syncthreads();
#pragma unroll
    for(int s=128;s>0;s>>=1){ if(t<s) red[t]+=red[t+s]; __syncthreads(); }
    float r=red[0]; __syncthreads(); return r;
}
__global__ void pi_kernel(const float* __restrict__ pm){
    __shared__ float su[256],sv[256],red[256];
    int b=blockIdx.x,t=threadIdx.x;
    unsigned idx=(unsigned)(b*256+t), x0=0u, x1=idx;
    threefry2x32(0u,1u,x0,x1);
    float f=__uint_as_float((x1>>9)|0x3f800000u)-1.0f;
    const float lo=-0.99999994f;
    float val=fmaxf(lo, f*(1.0f-lo)+lo);
    su[t]=1.41421354f*erfinv_f(val);
    __syncthreads();
    const float* A=pm+(size_t)b*MATSZ;
    float lastnorm=1.0f;
    for(int it=0;it<10;it++){
        float acc=0.0f;
        for(int i=0;i<256;i++) acc=fmaf(A[i*256+t],su[i],acc);
        float nv=sqrtf(block_sum256(acc*acc,red)); sv[t]=acc/nv; __syncthreads();
        float a2=0.0f;
        for(int j=0;j<256;j++) a2=fmaf(A[t*256+j],sv[j],a2);
        float nu=sqrtf(block_sum256(a2*a2,red)); su[t]=a2/nu; __syncthreads();
        lastnorm=nu;
    }
    if(t==0) g_s[b]=lastnorm;
}
__global__ void scale_kernel(const float* __restrict__ pm){
    int i=blockIdx.x*256+threadIdx.x;
    ((float*)g_wa)[i]=pm[i]/g_s[i>>16];
}

// ---------- Bjorck 32x32 (known-good) ----------
__global__ void __launch_bounds__(256) syrk_kernel(int phase){
    const float* W = phase?(const float*)g_wb:(const float*)g_wa;
    int b=blockIdx.z; const float* A=W+(size_t)b*MATSZ; float* C=(float*)g_wtw+(size_t)b*MATSZ;
    __shared__ __align__(8) float As[16][32],Bs[16][32];
    int I0=blockIdx.y*32,K0=blockIdx.x*32,tid=threadIdx.x;
    int jj=tid>>4,ii2=(tid&15)*2,tx=tid&15,ty=tid>>4;
    float acc[2][2]={};
    for(int j0=0;j0<256;j0+=16){
        *(float2*)&As[jj][ii2]=*(const float2*)&A[(j0+jj)*256+I0+ii2];
        *(float2*)&Bs[jj][ii2]=*(const float2*)&A[(j0+jj)*256+K0+ii2];
        __syncthreads();
#pragma unroll
        for(int kk=0;kk<16;kk++){
            float2 a=*(float2*)&As[kk][ty*2], bb=*(float2*)&Bs[kk][tx*2];
            acc[0][0]=fmaf(a.x,bb.x,acc[0][0]); acc[0][1]=fmaf(a.x,bb.y,acc[0][1]);
            acc[1][0]=fmaf(a.y,bb.x,acc[1][0]); acc[1][1]=fmaf(a.y,bb.y,acc[1][1]);
        }
        __syncthreads();
    }
#pragma unroll
    for(int r=0;r<2;r++){ float2 v; v.x=acc[r][0]; v.y=acc[r][1];
        *(float2*)&C[(I0+ty*2+r)*256+K0+tx*2]=v; }
}
__global__ void __launch_bounds__(256) update_kernel(int phase){
    const float* W = phase?(const float*)g_wb:(const float*)g_wa;
    float* O = phase?(float*)g_wa:(float*)g_wb;
    int b=blockIdx.z; const float* A=W+(size_t)b*MATSZ;
    const float* Bm=(const float*)g_wtw+(size_t)b*MATSZ; float* C=O+(size_t)b*MATSZ;
    __shared__ __align__(8) float As[16][32],Bs[16][32];
    int I0=blockIdx.y*32,K0=blockIdx.x*32,tid=threadIdx.x;
    int jj=tid>>4,kk2=(tid&15)*2,ar=tid>>3,ac2=(tid&7)*2,tx=tid&15,ty=tid>>4;
    float acc[2][2]={};
    for(int j0=0;j0<256;j0+=16){
        float2 av=*(const float2*)&A[(I0+ar)*256+j0+ac2];
        As[ac2+0][ar]=av.x; As[ac2+1][ar]=av.y;
        *(float2*)&Bs[jj][kk2]=*(const float2*)&Bm[(j0+jj)*256+K0+kk2];
        __syncthreads();
#pragma unroll
        for(int kk=0;kk<16;kk++){
            float2 a=*(float2*)&As[kk][ty*2], bb=*(float2*)&Bs[kk][tx*2];
            acc[0][0]=fmaf(a.x,bb.x,acc[0][0]); acc[0][1]=fmaf(a.x,bb.y,acc[0][1]);
            acc[1][0]=fmaf(a.y,bb.x,acc[1][0]); acc[1][1]=fmaf(a.y,bb.y,acc[1][1]);
        }
        __syncthreads();
    }
#pragma unroll
    for(int r=0;r<2;r++){
        float2 wv=*(const float2*)&A[(I0+ty*2+r)*256+K0+tx*2];
        float2 v; v.x=1.5f*wv.x-0.5f*acc[r][0]; v.y=1.5f*wv.y-0.5f*acc[r][1];
        *(float2*)&C[(I0+ty*2+r)*256+K0+tx*2]=v;
    }
}

// ---------- 64x64 GEMM helpers + chain ----------
#define FMA16(a,bb) do{ \
    acc[0][0]=fmaf(a.x,bb.x,acc[0][0]);acc[0][1]=fmaf(a.x,bb.y,acc[0][1]);acc[0][2]=fmaf(a.x,bb.z,acc[0][2]);acc[0][3]=fmaf(a.x,bb.w,acc[0][3]); \
    acc[1][0]=fmaf(a.y,bb.x,acc[1][0]);acc[1][1]=fmaf(a.y,bb.y,acc[1][1]);acc[1][2]=fmaf(a.y,bb.z,acc[1][2]);acc[1][3]=fmaf(a.y,bb.w,acc[1][3]); \
    acc[2][0]=fmaf(a.z,bb.x,acc[2][0]);acc[2][1]=fmaf(a.z,bb.y,acc[2][1]);acc[2][2]=fmaf(a.z,bb.z,acc[2][2]);acc[2][3]=fmaf(a.z,bb.w,acc[2][3]); \
    acc[3][0]=fmaf(a.w,bb.x,acc[3][0]);acc[3][1]=fmaf(a.w,bb.y,acc[3][1]);acc[3][2]=fmaf(a.w,bb.z,acc[3][2]);acc[3][3]=fmaf(a.w,bb.w,acc[3][3]); }while(0)
__device__ __forceinline__ void gemm_nn_tile(const float* __restrict__ A,const float* __restrict__ B,
        int I0,int K0,int Klen,float(&acc)[4][4],float(*As)[64],float(*Bs)[64]){
    int tid=threadIdx.x,lr=tid>>2,lc4=(tid&3)*4,bk=tid>>4,bi4=(tid&15)*4,tx=tid&15,ty=tid>>4;
    for(int j0=0;j0<Klen;j0+=16){
        float4 av=*(const float4*)&A[(I0+lr)*256+j0+lc4];
        As[lc4+0][lr]=av.x;As[lc4+1][lr]=av.y;As[lc4+2][lr]=av.z;As[lc4+3][lr]=av.w;
        *(float4*)&Bs[bk][bi4]=*(const float4*)&B[(j0+bk)*256+K0+bi4];
        __syncthreads();
#pragma unroll
        for(int kk=0;kk<16;kk++){ float4 a=*(float4*)&As[kk][ty*4],bb=*(float4*)&Bs[kk][tx*4]; FMA16(a,bb); }
        __syncthreads();
    }
}
__device__ __forceinline__ void gemm_nt_tile(const float* __restrict__ A,const float* __restrict__ B,
        int I0,int K0,int Klen,float(&acc)[4][4],float(*As)[64],float(*Bs)[64]){
    int tid=threadIdx.x,lr=tid>>2,lc4=(tid&3)*4,tx=tid&15,ty=tid>>4;
    for(int j0=0;j0<Klen;j0+=16){
        float4 av=*(const float4*)&A[(I0+lr)*256+j0+lc4];
        As[lc4+0][lr]=av.x;As[lc4+1][lr]=av.y;As[lc4+2][lr]=av.z;As[lc4+3][lr]=av.w;
        float4 bv=*(const float4*)&B[(K0+lr)*256+j0+lc4];
        Bs[lc4+0][lr]=bv.x;Bs[lc4+1][lr]=bv.y;Bs[lc4+2][lr]=bv.z;Bs[lc4+3][lr]=bv.w;
        __syncthreads();
#pragma unroll
        for(int kk=0;kk<16;kk++){ float4 a=*(float4*)&As[kk][ty*4],bb=*(float4*)&Bs[kk][tx*4]; FMA16(a,bb); }
        __syncthreads();
    }
}
__device__ __forceinline__ void store_tile(float* __restrict__ C,int I0,int K0,float(&acc)[4][4]){
    int tx=threadIdx.x&15,ty=threadIdx.x>>4;
#pragma unroll
    for(int r=0;r<4;r++){ float4 v; v.x=acc[r][0];v.y=acc[r][1];v.z=acc[r][2];v.w=acc[r][3];
        *(float4*)&C[(I0+ty*4+r)*256+K0+tx*4]=v; }
}
__global__ void pq_kernel(){
    int m=blockIdx.z; const float* A=(const float*)g_wa+(size_t)(1+m)*MATSZ;
    float* C=(float*)g_PQ+(size_t)m*MATSZ;
    __shared__ __align__(16) float As[16][64],Bs[16][64];
    int I0=blockIdx.y*64,K0=blockIdx.x*64; float acc[4][4]={};
    gemm_nt_tile(A,A,I0,K0,128,acc,As,Bs); store_tile(C,I0,K0,acc);
}
__global__ void c2_kernel(){
    int m=blockIdx.z;
    const float* A=(const float*)g_PQ+(size_t)(2*m)*MATSZ;
    const float* B=(const float*)g_PQ+(size_t)(2*m+1)*MATSZ;
    float* C=(float*)g_C2+(size_t)m*MATSZ;
    __shared__ __align__(16) float As[16][64],Bs[16][64];
    int I0=blockIdx.y*64,K0=blockIdx.x*64; float acc[4][4]={};
    gemm_nn_tile(A,B,I0,K0,256,acc,As,Bs); store_tile(C,I0,K0,acc);
}
__global__ void blk_kernel(){
    int e=blockIdx.x*256+threadIdx.x, m=e>>16, r=e&65535;
    float C=g_C2[m][r],P1=g_PQ[2*m][r],P2=g_PQ[2*m+1][r];
    float I=((r>>8)==(r&255))?1.0f:0.0f;
    g_blk[m][0][r]=C; g_blk[m][1][r]=P1-C; g_blk[m][2][r]=P2-C; g_blk[m][3][r]=I-P1-P2+C;
}
__global__ void mconv_kernel(){
    int z=blockIdx.z,i=z/3,j=z%3;
    __shared__ __align__(16) float As[16][64],Bs[16][64];
    int I0=blockIdx.y*64,K0=blockIdx.x*64; float acc[4][4]={};
    for(int i1=0;i1<2;i1++){ int di=i-i1; if(di<0||di>1) continue;
        for(int j1=0;j1<2;j1++){ int dj=j-j1; if(dj<0||dj>1) continue;
            const float* A=(const float*)g_blk+(size_t)(i1*2+j1)*MATSZ;
            const float* B=(const float*)g_blk+(size_t)(4+di*2+dj)*MATSZ;
            gemm_nn_tile(A,B,I0,K0,256,acc,As,Bs);
        }
    }
    store_tile((float*)g_p9+(size_t)z*MATSZ,I0,K0,acc);
}
__global__ void tmat_kernel(){
    int z2=blockIdx.z,kh=z2/3,kw=z2%3;
    const float* A=(const float*)g_wa;
    const float* B=(const float*)g_p9+(size_t)(kw*3+kh)*MATSZ;
    float* C=(float*)g_W9+(size_t)z2*MATSZ;
    __shared__ __align__(16) float As[16][64],Bs[16][64];
    int I0=blockIdx.y*64,K0=blockIdx.x*64; float acc[4][4]={};
    gemm_nn_tile(A,B,I0,K0,256,acc,As,Bs); store_tile(C,I0,K0,acc);
}

// ---------- bf16 splits ----------
__global__ void wsplit_kernel(){
    int z=blockIdx.x, ic=blockIdx.y, oc=threadIdx.x;
    float w=g_W9[z][ic*256+oc];
    __nv_bfloat16 hb=__float2bfloat16(w);
    __nv_bfloat16 lb=__float2bfloat16(w-__bfloat162float(hb));
    g_Whi[((size_t)z*256+oc)*256+ic]=*(unsigned short*)&hb;
    g_Wlo[((size_t)z*256+oc)*256+ic]=*(unsigned short*)&lb;
}
__global__ void __launch_bounds__(256) xsplit_kernel(const float* __restrict__ X){
    __shared__ float tile[64][65];
    int y=blockIdx.x,n=blockIdx.y,tid=threadIdx.x;
    int x=tid&63,q=tid>>6;
    for(int ic0=0;ic0<256;ic0+=64){
        __syncthreads();
        for(int i=0;i<16;i++){
            int idx=tid+i*256;
            tile[idx>>6][idx&63]=X[(((size_t)n*256+ic0+(idx>>6))*64+y)*64+(idx&63)];
        }
        __syncthreads();
        unsigned short h[16],l[16];
#pragma unroll
        for(int k=0;k<16;k++){
            float v=tile[q*16+k][x];
            __nv_bfloat16 hb=__float2bfloat16(v);
            __nv_bfloat16 lb=__float2bfloat16(v-__bfloat162float(hb));
            h[k]=*(unsigned short*)&hb; l[k]=*(unsigned short*)&lb;
        }
        size_t base=(((size_t)n*64+y)*64+x)*256+ic0+q*16;
        *(uint4*)(g_Xhi+base)=*(uint4*)h; *(uint4*)(g_Xhi+base+8)=*(uint4*)(h+8);
        *(uint4*)(g_Xlo+base)=*(uint4*)l; *(uint4*)(g_Xlo+base+8)=*(uint4*)(l+8);
    }
}

// ---------- wmma conv: 128 px x 128 oc per CTA, bf16 hi/lo split ----
#define LDK 72                    // bf16 elems per smem row (64 + 8 pad)
#define OFF_AHI 0
#define OFF_ALO 18432
#define OFF_BHI 36864
#define OFF_BLO 55296
#define SMEM_WMMA 73728           // also reused as Cs[128][136] f32 (69632 B)
__global__ void __launch_bounds__(256) conv_wmma(const float* __restrict__ bias,
                                                 float* __restrict__ out){
    extern __shared__ __align__(16) unsigned char sm[];
    __nv_bfloat16* Ah=(__nv_bfloat16*)(sm+OFF_AHI);
    __nv_bfloat16* Al=(__nv_bfloat16*)(sm+OFF_ALO);
    __nv_bfloat16* Bh=(__nv_bfloat16*)(sm+OFF_BHI);
    __nv_bfloat16* Bl=(__nv_bfloat16*)(sm+OFF_BLO);
    float* Cs=(float*)sm;

    int tid=threadIdx.x, wid=tid>>5;
    int p=blockIdx.x, ocb=blockIdx.y, n=blockIdx.z;
    int wm=wid&1, wn=wid>>1;              // warp tile: 64 px x 32 oc

    wmma::fragment<wmma::accumulator,16,16,16,float> c[4][2];
#pragma unroll
    for(int mi=0;mi<4;mi++)
#pragma unroll
        for(int ni=0;ni<2;ni++) wmma::fill_fragment(c[mi][ni],0.0f);

    int e=tid, px=e>>1, half=e&1;         // A loader: px row, 32-ic half
    int r=px>>6, x=px&63;

    for(int st=0;st<36;st++){
        int z=st>>2, ic0=(st&3)*64, dy=z/3, dx=z%3;
        // stage A (128 px x 64 ic, hi+lo)
        {
            int gy=(2*p+r+dy+63)&63, gx=(x+dx+63)&63;
            size_t xoff=((((size_t)n*64+gy)*64+gx)<<8)+ic0+half*32;
            const uint4* sh=(const uint4*)(g_Xhi+xoff);
            const uint4* sl=(const uint4*)(g_Xlo+xoff);
            uint4* dh=(uint4*)(Ah+px*LDK+half*32);
            uint4* dl=(uint4*)(Al+px*LDK+half*32);
#pragma unroll
            for(int j=0;j<4;j++){ dh[j]=sh[j]; dl[j]=sl[j]; }
        }
        // stage B (128 oc x 64 ic, hi+lo)
        {
            int oc=px;
            size_t woff=(((size_t)z*256+ocb*128+oc)<<8)+ic0+half*32;
            const uint4* sh=(const uint4*)(g_Whi+woff);
            const uint4* sl=(const uint4*)(g_Wlo+woff);
            uint4* dh=(uint4*)(Bh+oc*LDK+half*32);
            uint4* dl=(uint4*)(Bl+oc*LDK+half*32);
#pragma unroll
            for(int j=0;j<4;j++){ dh[j]=sh[j]; dl[j]=sl[j]; }
        }
        __syncthreads();
#pragma unroll
        for(int kf=0;kf<4;kf++){
            wmma::fragment<wmma::matrix_a,16,16,16,__nv_bfloat16,wmma::row_major> ah[4],al[4];
            wmma::fragment<wmma::matrix_b,16,16,16,__nv_bfloat16,wmma::col_major> bh[2],bl[2];
#pragma unroll
            for(int mi=0;mi<4;mi++){
                const __nv_bfloat16* ap=Ah+(wm*64+mi*16)*LDK+kf*16;
                wmma::load_matrix_sync(ah[mi],ap,LDK);
                wmma::load_matrix_sync(al[mi],ap+(OFF_ALO-OFF_AHI)/2,LDK);
            }
#pragma unroll
            for(int ni=0;ni<2;ni++){
                const __nv_bfloat16* bp=Bh+(wn*32+ni*16)*LDK+kf*16;
                wmma::load_matrix_sync(bh[ni],bp,LDK);
                wmma::load_matrix_sync(bl[ni],bp+(OFF_BLO-OFF_BHI)/2,LDK);
            }
#pragma unroll
            for(int mi=0;mi<4;mi++)
#pragma unroll
                for(int ni=0;ni<2;ni++){
                    wmma::mma_sync(c[mi][ni],ah[mi],bh[ni],c[mi][ni]);
                    wmma::mma_sync(c[mi][ni],al[mi],bh[ni],c[mi][ni]);
                    wmma::mma_sync(c[mi][ni],ah[mi],bl[ni],c[mi][ni]);
                }
        }
        __syncthreads();
    }

    // epilogue: C frags -> smem -> global (coalesced), + bias
#pragma unroll
    for(int mi=0;mi<4;mi++)
#pragma unroll
        for(int ni=0;ni<2;ni++)
            wmma::store_matrix_sync(&Cs[(size_t)(wm*64+mi*16)*136+wn*32+ni*16],
                                    c[mi][ni],136,wmma::mem_row_major);
    __syncthreads();
    for(int i=0;i<64;i++){
        int idx=tid+i*256;
        int oc=idx>>7, pp=idx&127;
        int rr=pp>>6, xx=pp&63, y=2*p+rr;
        int goc=ocb*128+oc;
        out[(((size_t)n*256+goc)<<12)+y*64+xx]=Cs[(size_t)pp*136+oc]+__ldg(&bias[goc]);
    }
}

// ------------------------------------------------------------------
extern "C" void kernel_launch(void* const* d_in, const int* in_sizes, int n_in,
                              void* d_out, int out_size){
    const float *x=nullptr,*pm=nullptr,*bias=nullptr;
    for(int i=0;i<n_in;i++){
        if(in_sizes[i]==16*256*64*64) x=(const float*)d_in[i];
        else if(in_sizes[i]==5*256*256) pm=(const float*)d_in[i];
        else if(in_sizes[i]==256) bias=(const float*)d_in[i];
    }
    float* out=(float*)d_out;
    cudaFuncSetAttribute(conv_wmma, cudaFuncAttributeMaxDynamicSharedMemorySize, SMEM_WMMA);

    pi_kernel<<<5,256>>>(pm);
    scale_kernel<<<1280,256>>>(pm);
    for(int it=0;it<20;++it){
        syrk_kernel<<<dim3(8,8,5),256>>>(it&1);
        update_kernel<<<dim3(8,8,5),256>>>(it&1);
    }
    xsplit_kernel<<<dim3(64,16),256>>>(x);
    pq_kernel<<<dim3(4,4,4),256>>>();
    c2_kernel<<<dim3(4,4,2),256>>>();
    blk_kernel<<<512,256>>>();
    mconv_kernel<<<dim3(4,4,9),256>>>();
    tmat_kernel<<<dim3(4,4,9),256>>>();
    wsplit_kernel<<<dim3(9,256),256>>>();
    conv_wmma<<<dim3(32,2,16),256,SMEM_WMMA>>>(bias,out);
}